// round 9
// baseline (speedup 1.0000x reference)
#include <cuda_runtime.h>
#include <cuda_bf16.h>
#include <stdint.h>
#include <math.h>

#define BATCH 2
#define CH    256
#define HH    96
#define WW    96
#define HW    (HH*WW)        // 9216
#define OUTC  256
#define KTAPS 9
#define KDIM  (KTAPS*CH)     // 2304
#define MROWS (BATCH*HW)     // 18432
#define NOFF  32             // 27 padded to 32

#define SW128(o) ((o) ^ ((((o) >> 3) & 0x70)))

struct __align__(16) SInfo { int i0,i1,i2,i3; float w0,w1,w2,w3; };

// ---- scratch (device globals: allocation-free) ----
__device__ float g_xT [MROWS*CH];        // x NHWC fp32
__device__ float g_h1T[MROWS*CH];        // layer-1 out NHWC fp32
__device__ float g_h2T[MROWS*CH];        // layer-2 out NHWC fp32
__device__ float g_om [MROWS*NOFF];      // offset-conv out (27 used)
__device__ SInfo g_sinfo[MROWS*KTAPS];   // bilinear indices+weights
__device__ float g_bwoff[2][KDIM*NOFF];  // offset weights, K-major [k][j]
// main weights in mma-B-fragment order, bf16 hi/lo:
//   [layer][blk36 = tap*4+g][kb4][nbAll32][lane32] uint2{pack(k0,k1), pack(k0+8,k1+8)}
__device__ uint2 g_bwmh[2*36*4096];
__device__ uint2 g_bwml[2*36*4096];

// ====================== helpers ======================
__device__ __forceinline__ uint32_t smem_u32(const void* p) {
    uint32_t a;
    asm("{ .reg .u64 t; cvta.to.shared.u64 t, %1; cvt.u32.u64 %0, t; }" : "=r"(a) : "l"(p));
    return a;
}

__device__ __forceinline__ void split_bf16(float v, uint16_t& h, uint16_t& l) {
    __nv_bfloat16 hb = __float2bfloat16_rn(v);
    float lo = v - __bfloat162float(hb);
    __nv_bfloat16 lb = __float2bfloat16_rn(lo);
    h = __bfloat16_as_ushort(hb);
    l = __bfloat16_as_ushort(lb);
}

#define LDSM4(r0,r1,r2,r3, addr)                                                    \
    asm volatile("ldmatrix.sync.aligned.m8n8.x4.shared.b16 {%0,%1,%2,%3}, [%4];"    \
        : "=r"(r0), "=r"(r1), "=r"(r2), "=r"(r3) : "r"(addr))

#define MMA16816(d, a0,a1,a2,a3, b0,b1)                                             \
    asm volatile("mma.sync.aligned.m16n8k16.row.col.f32.bf16.bf16.f32 "             \
        "{%0,%1,%2,%3}, {%4,%5,%6,%7}, {%8,%9}, {%0,%1,%2,%3};"                     \
        : "+f"((d)[0]), "+f"((d)[1]), "+f"((d)[2]), "+f"((d)[3])                    \
        : "r"(a0), "r"(a1), "r"(a2), "r"(a3), "r"(b0), "r"(b1))

#define CP_ASYNC16(dst, src) \
    asm volatile("cp.async.cg.shared.global [%0], [%1], 16;" :: "r"(dst), "l"(src))
#define CP_COMMIT() asm volatile("cp.async.commit_group;" ::: "memory")
#define CP_WAIT0()  asm volatile("cp.async.wait_group 0;" ::: "memory")

// ====================== weight prep ======================
__global__ void prep_woff_k(const float* __restrict__ woff, int layer) {
    int idx = blockIdx.x*256 + threadIdx.x;
    if (idx >= KDIM*NOFF) return;
    int j   = idx & 31;
    int kc  = idx >> 5;
    int tap = kc / CH, c = kc % CH;
    g_bwoff[layer][idx] = (j < 27) ? woff[(j*CH + c)*KTAPS + tap] : 0.0f;
}

__global__ void prep_main_mma(const float* __restrict__ w, int layer) {
    int idx = blockIdx.x*256 + threadIdx.x;           // 36*4096 = 147456
    if (idx >= 36*4096) return;
    int lane = idx & 31;
    int nb   = (idx >> 5) & 31;
    int kb   = (idx >> 10) & 3;
    int blk  = idx >> 12;
    int tap  = blk >> 2, g = blk & 3;
    int n    = nb*8 + (lane >> 2);
    int c0   = g*64 + kb*16 + (lane & 3)*2;
    const float* wb = w + (size_t)n*CH*KTAPS + tap;
    float v00 = wb[(size_t)(c0    )*KTAPS];
    float v01 = wb[(size_t)(c0 + 1)*KTAPS];
    float v10 = wb[(size_t)(c0 + 8)*KTAPS];
    float v11 = wb[(size_t)(c0 + 9)*KTAPS];
    uint16_t h00,l00,h01,l01,h10,l10,h11,l11;
    split_bf16(v00,h00,l00); split_bf16(v01,h01,l01);
    split_bf16(v10,h10,l10); split_bf16(v11,h11,l11);
    size_t o = (size_t)layer*36*4096 + idx;
    g_bwmh[o] = make_uint2((uint32_t)h00 | ((uint32_t)h01 << 16),
                           (uint32_t)h10 | ((uint32_t)h11 << 16));
    g_bwml[o] = make_uint2((uint32_t)l00 | ((uint32_t)l01 << 16),
                           (uint32_t)l10 | ((uint32_t)l11 << 16));
}

// ====================== layout transposes ======================
__global__ void nchw_to_nhwc_k(const float* __restrict__ src) {
    __shared__ float t[32][33];
    int b  = blockIdx.z;
    int p0 = blockIdx.x*32, c0 = blockIdx.y*32;
    int tx = threadIdx.x,  ty = threadIdx.y;
    #pragma unroll
    for (int i = 0; i < 32; i += 8)
        t[ty+i][tx] = src[(size_t)(b*CH + c0+ty+i)*HW + p0 + tx];
    __syncthreads();
    #pragma unroll
    for (int i = 0; i < 32; i += 8)
        g_xT[(size_t)(b*HW + p0+ty+i)*CH + c0 + tx] = t[tx][ty+i];
}

__global__ void nhwc_to_nchw_k(float* __restrict__ dst) {
    __shared__ float t[32][33];
    int b  = blockIdx.z;
    int p0 = blockIdx.x*32, c0 = blockIdx.y*32;
    int tx = threadIdx.x,  ty = threadIdx.y;
    #pragma unroll
    for (int i = 0; i < 32; i += 8)
        t[ty+i][tx] = g_h2T[(size_t)(b*HW + p0+ty+i)*CH + c0 + tx];
    __syncthreads();
    #pragma unroll
    for (int i = 0; i < 32; i += 8)
        dst[(size_t)(b*CH + c0+ty+i)*HW + p0 + tx] = t[tx][ty+i];
}

// ====================== offset conv: fp32 SIMT implicit GEMM ======================
__launch_bounds__(256, 2)
__global__ void gemm_off_k(int layer, const float* __restrict__ bias) {
    __shared__ float As[32][128];
    __shared__ float Bs[32][32];
    const float* in = (layer == 0) ? g_xT : g_h1T;
    const float* Bw = g_bwoff[layer];
    int tid = threadIdx.x;
    int bm  = blockIdx.x;
    int ty  = tid >> 3, tx = tid & 7;
    int px  = tid & 127, cg = tid >> 7;
    int cc  = cg * 16;
    int gp  = bm*128 + px;
    int b   = gp / HW, p = gp % HW;
    int y   = p / WW, x = p % WW;
    const float* inb = in + (size_t)b*HW*CH;

    float acc[4][4] = {};

    for (int kt = 0; kt < 72; kt++) {
        int tap = kt >> 3;
        int c0  = (kt & 7) * 32;
        float4 bfrag = ((const float4*)(Bw + (size_t)(tap*CH + c0)*NOFF))[tid];
        int ny = y + tap/3 - 1;
        int nx = x + tap%3 - 1;
        float4 d0 = {0,0,0,0}, d1 = d0, d2 = d0, d3 = d0;
        if ((unsigned)ny < HH && (unsigned)nx < WW) {
            const float* s = inb + (size_t)(ny*WW + nx)*CH + c0 + cc;
            d0 = *(const float4*)(s);
            d1 = *(const float4*)(s + 4);
            d2 = *(const float4*)(s + 8);
            d3 = *(const float4*)(s + 12);
        }
        __syncthreads();
        As[cc+ 0][px]=d0.x; As[cc+ 1][px]=d0.y; As[cc+ 2][px]=d0.z; As[cc+ 3][px]=d0.w;
        As[cc+ 4][px]=d1.x; As[cc+ 5][px]=d1.y; As[cc+ 6][px]=d1.z; As[cc+ 7][px]=d1.w;
        As[cc+ 8][px]=d2.x; As[cc+ 9][px]=d2.y; As[cc+10][px]=d2.z; As[cc+11][px]=d2.w;
        As[cc+12][px]=d3.x; As[cc+13][px]=d3.y; As[cc+14][px]=d3.z; As[cc+15][px]=d3.w;
        ((float4*)Bs)[tid] = bfrag;
        __syncthreads();

        #pragma unroll
        for (int kk = 0; kk < 32; kk++) {
            float a[4], bb[4];
            *(float4*)a  = *(const float4*)&As[kk][ty*4];
            *(float4*)bb = *(const float4*)&Bs[kk][tx*4];
            #pragma unroll
            for (int i = 0; i < 4; i++)
                #pragma unroll
                for (int j = 0; j < 4; j++)
                    acc[i][j] += a[i]*bb[j];
        }
    }

    int j0 = tx*4;
    float bv[4];
    #pragma unroll
    for (int j = 0; j < 4; j++) bv[j] = (j0 + j < 27) ? bias[j0 + j] : 0.0f;
    #pragma unroll
    for (int i = 0; i < 4; i++) {
        int row = bm*128 + ty*4 + i;
        float4 o4 = make_float4(acc[i][0]+bv[0], acc[i][1]+bv[1],
                                acc[i][2]+bv[2], acc[i][3]+bv[3]);
        *(float4*)&g_om[(size_t)row*NOFF + j0] = o4;
    }
}

// ====================== sample coordinates + bilinear weights ======================
__global__ void coords_k() {
    int idx = blockIdx.x*256 + threadIdx.x;
    if (idx >= MROWS*KTAPS) return;
    int tap = idx % KTAPS;
    int gp  = idx / KTAPS;
    int p   = gp % HW;
    int y   = p / WW, x = p % WW;
    const float* om = g_om + (size_t)gp*NOFF;
    float dy = om[2*tap], dx = om[2*tap + 1];
    float m  = 1.0f / (1.0f + expf(-om[18 + tap]));
    float ys = (float)(y + tap/3 - 1) + dy;
    float xs = (float)(x + tap%3 - 1) + dx;
    float fy0 = floorf(ys), fx0 = floorf(xs);
    int y0 = (int)fy0, x0 = (int)fx0;
    int y1 = y0 + 1,   x1 = x0 + 1;
    float wy1 = ys - fy0, wx1 = xs - fx0;
    float wy0 = 1.0f - wy1, wx0 = 1.0f - wx1;
    int y0c = min(max(y0,0),HH-1), y1c = min(max(y1,0),HH-1);
    int x0c = min(max(x0,0),WW-1), x1c = min(max(x1,0),WW-1);
    float vy0 = ((unsigned)y0 < HH) ? 1.0f : 0.0f;
    float vy1 = ((unsigned)y1 < HH) ? 1.0f : 0.0f;
    float vx0 = ((unsigned)x0 < WW) ? 1.0f : 0.0f;
    float vx1 = ((unsigned)x1 < WW) ? 1.0f : 0.0f;
    SInfo s;
    s.i0 = y0c*WW + x0c;  s.w0 = wy0*wx0*m*vy0*vx0;
    s.i1 = y0c*WW + x1c;  s.w1 = wy0*wx1*m*vy0*vx1;
    s.i2 = y1c*WW + x0c;  s.w2 = wy1*wx0*m*vy1*vx0;
    s.i3 = y1c*WW + x1c;  s.w3 = wy1*wx1*m*vy1*vx1;
    g_sinfo[idx] = s;
}

// ====================== main deformable conv: mma.sync bf16x3, double-buffered ======================
// CTA: 128 px (M) x 128 out-ch (N), grid (144, 2). 8 warps, warp tile 64x32.
// Two 64KB smem buffers; per stage: issue cp.async B + gather A for stage s+1,
// run MMAs for stage s, store A regs, cp.wait + one sync.
#define SA_H 0
#define SA_L 16384
#define SB_H 32768
#define SB_L 49152
#define BUFB 65536
#define MAIN_SMEM (2*BUFB + 1024)
#define NSTAGE 36

__launch_bounds__(256, 1)
__global__ void gemm_main_mma(int layer) {
    extern __shared__ unsigned char dsm[];
    uint32_t raw = smem_u32(dsm);
    uint32_t sb  = (raw + 1023u) & ~1023u;      // 1024-aligned shared addr
    unsigned char* smp = dsm + (sb - raw);      // matching generic pointer

    int tid  = threadIdx.x;
    int wid  = tid >> 5, lane = tid & 31;
    int wm   = wid & 1;                          // M warp (0..1) -> 64 rows
    int wn   = wid >> 1;                         // N warp (0..3) -> 32 cols
    int bm   = blockIdx.x;                       // 144 M tiles
    int half = blockIdx.y;                       // N half (0..1)

    const float* in   = layer ? g_h1T : g_xT;
    float*       outF = layer ? g_h2T : g_h1T;
    const uint2* bwh  = g_bwmh + (size_t)layer*36*4096;
    const uint2* bwl  = g_bwml + (size_t)layer*36*4096;

    int c4 = tid & 15;                           // channel quad (16 x 4 = 64 ch)
    int pg = tid >> 4;                           // pixel group (16 x 8 = 128 px)
    int b  = (bm*128) / HW;
    const float* inb = in + (size_t)b*HW*CH;
    const SInfo* sinf = g_sinfo + (size_t)(bm*128)*KTAPS;

    float acc[4][4][4];
    #pragma unroll
    for (int i = 0; i < 4; i++)
        #pragma unroll
        for (int j = 0; j < 4; j++)
            #pragma unroll
            for (int k = 0; k < 4; k++) acc[i][j][k] = 0.0f;

    int rowsel = lane & 15, colh = lane >> 4;
    uint32_t a_rel = (uint32_t)((wm*64 + rowsel)*128 + colh*16);

    float v[32];   // staged A values (8 px x 4 ch, blended fp32)

    // ---- stage helpers (macros keep everything in registers) ----
    #define ISSUE_B(S, BUF) do {                                                     \
        int _blk = ((S) % 9)*4 + ((S) / 9);                                          \
        const uint4* _sH = (const uint4*)(bwh + (size_t)_blk*4096);                  \
        const uint4* _sL = (const uint4*)(bwl + (size_t)_blk*4096);                  \
        uint32_t _dst = sb + (BUF)*BUFB;                                             \
        _Pragma("unroll")                                                            \
        for (int _it = 0; _it < 4; _it++) {                                          \
            uint32_t _u  = tid + _it*256;                                            \
            uint32_t _kb = _u >> 8;                                                  \
            uint32_t _si = _kb*512 + (uint32_t)half*256 + (_u & 255);                \
            CP_ASYNC16(_dst + SB_H + _u*16, (const void*)(_sH + _si));               \
            CP_ASYNC16(_dst + SB_L + _u*16, (const void*)(_sL + _si));               \
        }                                                                            \
        CP_COMMIT();                                                                 \
    } while (0)

    #define GATHER_A(S) do {                                                         \
        int _tap = (S) % 9, _g = (S) / 9;                                            \
        int _cc  = _g*64 + c4*4;                                                     \
        _Pragma("unroll")                                                            \
        for (int _i = 0; _i < 8; _i++) {                                             \
            int _px = pg*8 + _i;                                                     \
            SInfo _s = sinf[_px*KTAPS + _tap];                                       \
            float4 _a0 = *(const float4*)(inb + (size_t)_s.i0*CH + _cc);             \
            float4 _a1 = *(const float4*)(inb + (size_t)_s.i1*CH + _cc);             \
            float4 _a2 = *(const float4*)(inb + (size_t)_s.i2*CH + _cc);             \
            float4 _a3 = *(const float4*)(inb + (size_t)_s.i3*CH + _cc);             \
            v[_i*4+0] = _s.w0*_a0.x + _s.w1*_a1.x + _s.w2*_a2.x + _s.w3*_a3.x;       \
            v[_i*4+1] = _s.w0*_a0.y + _s.w1*_a1.y + _s.w2*_a2.y + _s.w3*_a3.y;       \
            v[_i*4+2] = _s.w0*_a0.z + _s.w1*_a1.z + _s.w2*_a2.z + _s.w3*_a3.z;       \
            v[_i*4+3] = _s.w0*_a0.w + _s.w1*_a1.w + _s.w2*_a2.w + _s.w3*_a3.w;       \
        }                                                                            \
    } while (0)

    #define STORE_A(BUF) do {                                                        \
        unsigned char* _bp = smp + (BUF)*BUFB;                                       \
        _Pragma("unroll")                                                            \
        for (int _i = 0; _i < 8; _i++) {                                             \
            int _px = pg*8 + _i;                                                     \
            uint16_t _h0,_l0,_h1,_l1,_h2,_l2,_h3,_l3;                                \
            split_bf16(v[_i*4+0],_h0,_l0); split_bf16(v[_i*4+1],_h1,_l1);            \
            split_bf16(v[_i*4+2],_h2,_l2); split_bf16(v[_i*4+3],_h3,_l3);            \
            uint32_t _so = SW128((uint32_t)(_px*128 + c4*8));                        \
            *(uint2*)(_bp + SA_H + _so) =                                            \
                make_uint2((uint32_t)_h0 | ((uint32_t)_h1 << 16),                    \
                           (uint32_t)_h2 | ((uint32_t)_h3 << 16));                   \
            *(uint2*)(_bp + SA_L + _so) =                                            \
                make_uint2((uint32_t)_l0 | ((uint32_t)_l1 << 16),                    \
                           (uint32_t)_l2 | ((uint32_t)_l3 << 16));                   \
        }                                                                            \
    } while (0)

    // ---- prologue: fill buffer 0 with stage 0 ----
    ISSUE_B(0, 0);
    GATHER_A(0);
    STORE_A(0);
    CP_WAIT0();
    __syncthreads();

    #pragma unroll 1
    for (int s = 0; s < NSTAGE; s++) {
        int cbuf = s & 1, nbuf = (s + 1) & 1;

        if (s + 1 < NSTAGE) {
            ISSUE_B(s + 1, nbuf);
            GATHER_A(s + 1);
        }

        // ---- compute stage s from cbuf ----
        {
            uint32_t abase = sb + cbuf*BUFB;
            unsigned char* bp = smp + cbuf*BUFB;
            #pragma unroll
            for (int kb = 0; kb < 4; kb++) {
                uint2 bh[4], bl[4];
                #pragma unroll
                for (int nb = 0; nb < 4; nb++) {
                    uint32_t boff = (uint32_t)(((kb*16 + wn*4 + nb)*32 + lane)*8);
                    bh[nb] = *(const uint2*)(bp + SB_H + boff);
                    bl[nb] = *(const uint2*)(bp + SB_L + boff);
                }
                #pragma unroll
                for (int mi = 0; mi < 4; mi++) {
                    uint32_t aoff = SW128(a_rel + (uint32_t)(mi*2048 + kb*32));
                    uint32_t ah0,ah1,ah2,ah3, al0,al1,al2,al3;
                    LDSM4(ah0,ah1,ah2,ah3, abase + SA_H + aoff);
                    LDSM4(al0,al1,al2,al3, abase + SA_L + aoff);
                    #pragma unroll
                    for (int nb = 0; nb < 4; nb++) {
                        MMA16816(acc[mi][nb], ah0,ah1,ah2,ah3, bh[nb].x, bh[nb].y);
                        MMA16816(acc[mi][nb], al0,al1,al2,al3, bh[nb].x, bh[nb].y);
                        MMA16816(acc[mi][nb], ah0,ah1,ah2,ah3, bl[nb].x, bl[nb].y);
                    }
                }
            }
        }

        if (s + 1 < NSTAGE) STORE_A(nbuf);
        CP_WAIT0();
        __syncthreads();
    }

    // ---- epilogue: ReLU, fp32 NHWC
    int crow = lane >> 2, ccol = (lane & 3)*2;
    #pragma unroll
    for (int mi = 0; mi < 4; mi++) {
        int px0 = bm*128 + wm*64 + mi*16;
        #pragma unroll
        for (int nb = 0; nb < 4; nb++) {
            int n = half*128 + wn*32 + nb*8 + ccol;
            float* o0 = outF + (size_t)(px0 + crow    )*OUTC + n;
            float* o1 = outF + (size_t)(px0 + crow + 8)*OUTC + n;
            float2 r0 = make_float2(fmaxf(acc[mi][nb][0], 0.f), fmaxf(acc[mi][nb][1], 0.f));
            float2 r1 = make_float2(fmaxf(acc[mi][nb][2], 0.f), fmaxf(acc[mi][nb][3], 0.f));
            *(float2*)o0 = r0;
            *(float2*)o1 = r1;
        }
    }
    #undef ISSUE_B
    #undef GATHER_A
    #undef STORE_A
}

// ====================== launch ======================
extern "C" void kernel_launch(void* const* d_in, const int* in_sizes, int n_in,
                              void* d_out, int out_size) {
    (void)in_sizes; (void)n_in; (void)out_size;
    const float* x      = (const float*)d_in[0];
    const float* w_off0 = (const float*)d_in[1];
    const float* b_off0 = (const float*)d_in[2];
    const float* w0     = (const float*)d_in[3];
    const float* w_off1 = (const float*)d_in[4];
    const float* b_off1 = (const float*)d_in[5];
    const float* w1     = (const float*)d_in[6];
    float* out = (float*)d_out;

    cudaFuncSetAttribute(gemm_main_mma, cudaFuncAttributeMaxDynamicSharedMemorySize, MAIN_SMEM);

    prep_woff_k  <<<(KDIM*NOFF + 255)/256, 256>>>(w_off0, 0);
    prep_woff_k  <<<(KDIM*NOFF + 255)/256, 256>>>(w_off1, 1);
    prep_main_mma<<<(36*4096 + 255)/256, 256>>>(w0, 0);
    prep_main_mma<<<(36*4096 + 255)/256, 256>>>(w1, 1);

    dim3 tb(32, 8);
    dim3 tg(HW/32, CH/32, BATCH);
    nchw_to_nhwc_k<<<tg, tb>>>(x);

    dim3 mg(MROWS/128, 2);

    // layer 1
    gemm_off_k   <<<MROWS/128, 256>>>(0, b_off0);
    coords_k     <<<(MROWS*KTAPS + 255)/256, 256>>>();
    gemm_main_mma<<<mg, 256, MAIN_SMEM>>>(0);

    // layer 2
    gemm_off_k   <<<MROWS/128, 256>>>(1, b_off1);
    coords_k     <<<(MROWS*KTAPS + 255)/256, 256>>>();
    gemm_main_mma<<<mg, 256, MAIN_SMEM>>>(1);

    nhwc_to_nchw_k<<<tg, tb>>>(out);
}

// round 11
// speedup vs baseline: 1.5925x; 1.5925x over previous
#include <cuda_runtime.h>
#include <cuda_bf16.h>
#include <stdint.h>
#include <math.h>

#define BATCH 2
#define CH    256
#define HH    96
#define WW    96
#define HW    (HH*WW)        // 9216
#define OUTC  256
#define KTAPS 9
#define KDIM  (KTAPS*CH)     // 2304
#define MROWS (BATCH*HW)     // 18432
#define NOFF  32             // 27 padded to 32

#define SW128(o) ((o) ^ ((((o) >> 3) & 0x70)))

struct __align__(16) SInfo { int i0,i1,i2,i3; float w0,w1,w2,w3; };

// ---- scratch (device globals: allocation-free) ----
__device__ float g_xT [MROWS*CH];        // x NHWC fp32
__device__ float g_h1T[MROWS*CH];        // layer-1 out NHWC fp32
__device__ float g_h2T[MROWS*CH];        // layer-2 out NHWC fp32
__device__ float g_om [MROWS*NOFF];      // offset-conv out (27 used)
__device__ SInfo g_sinfo[MROWS*KTAPS];   // bilinear indices+weights
// main weights in mma-B-fragment order, bf16 hi/lo:
//   [layer][blk36 = tap*4+g][kb4][nb32][lane32] uint2{pack(k0,k1), pack(k0+8,k1+8)}
__device__ uint2 g_bwmh[2*36*4096];
__device__ uint2 g_bwml[2*36*4096];
// offset weights, same frag order, N=32: [layer][blk36][kb4][nb4][lane32]
__device__ uint2 g_bwoh[2*36*512];
__device__ uint2 g_bwol[2*36*512];

// ====================== helpers ======================
__device__ __forceinline__ uint32_t smem_u32(const void* p) {
    uint32_t a;
    asm("{ .reg .u64 t; cvta.to.shared.u64 t, %1; cvt.u32.u64 %0, t; }" : "=r"(a) : "l"(p));
    return a;
}

__device__ __forceinline__ void split_bf16(float v, uint16_t& h, uint16_t& l) {
    __nv_bfloat16 hb = __float2bfloat16_rn(v);
    float lo = v - __bfloat162float(hb);
    __nv_bfloat16 lb = __float2bfloat16_rn(lo);
    h = __bfloat16_as_ushort(hb);
    l = __bfloat16_as_ushort(lb);
}

#define LDSM4(r0,r1,r2,r3, addr)                                                    \
    asm volatile("ldmatrix.sync.aligned.m8n8.x4.shared.b16 {%0,%1,%2,%3}, [%4];"    \
        : "=r"(r0), "=r"(r1), "=r"(r2), "=r"(r3) : "r"(addr))

#define MMA16816(d, a0,a1,a2,a3, b0,b1)                                             \
    asm volatile("mma.sync.aligned.m16n8k16.row.col.f32.bf16.bf16.f32 "             \
        "{%0,%1,%2,%3}, {%4,%5,%6,%7}, {%8,%9}, {%0,%1,%2,%3};"                     \
        : "+f"((d)[0]), "+f"((d)[1]), "+f"((d)[2]), "+f"((d)[3])                    \
        : "r"(a0), "r"(a1), "r"(a2), "r"(a3), "r"(b0), "r"(b1))

#define CP_ASYNC16(dst, src) \
    asm volatile("cp.async.cg.shared.global [%0], [%1], 16;" :: "r"(dst), "l"(src))
#define CP_COMMIT() asm volatile("cp.async.commit_group;" ::: "memory")
#define CP_WAIT0()  asm volatile("cp.async.wait_group 0;" ::: "memory")

// ====================== weight prep ======================
__global__ void prep_main_mma(const float* __restrict__ w, int layer) {
    int idx = blockIdx.x*256 + threadIdx.x;           // 36*4096 = 147456
    if (idx >= 36*4096) return;
    int lane = idx & 31;
    int nb   = (idx >> 5) & 31;
    int kb   = (idx >> 10) & 3;
    int blk  = idx >> 12;
    int tap  = blk >> 2, g = blk & 3;
    int n    = nb*8 + (lane >> 2);
    int c0   = g*64 + kb*16 + (lane & 3)*2;
    const float* wb = w + (size_t)n*CH*KTAPS + tap;
    float v00 = wb[(size_t)(c0    )*KTAPS];
    float v01 = wb[(size_t)(c0 + 1)*KTAPS];
    float v10 = wb[(size_t)(c0 + 8)*KTAPS];
    float v11 = wb[(size_t)(c0 + 9)*KTAPS];
    uint16_t h00,l00,h01,l01,h10,l10,h11,l11;
    split_bf16(v00,h00,l00); split_bf16(v01,h01,l01);
    split_bf16(v10,h10,l10); split_bf16(v11,h11,l11);
    size_t o = (size_t)layer*36*4096 + idx;
    g_bwmh[o] = make_uint2((uint32_t)h00 | ((uint32_t)h01 << 16),
                           (uint32_t)h10 | ((uint32_t)h11 << 16));
    g_bwml[o] = make_uint2((uint32_t)l00 | ((uint32_t)l01 << 16),
                           (uint32_t)l10 | ((uint32_t)l11 << 16));
}

__global__ void prep_off_mma(const float* __restrict__ woff, int layer) {
    int idx = blockIdx.x*256 + threadIdx.x;           // 36*512 = 18432
    if (idx >= 36*512) return;
    int lane = idx & 31;
    int nb   = (idx >> 5) & 3;
    int kb   = (idx >> 7) & 3;
    int blk  = idx >> 9;
    int tap  = blk >> 2, g = blk & 3;
    int n    = nb*8 + (lane >> 2);
    int c0   = g*64 + kb*16 + (lane & 3)*2;
    float v00 = 0.f, v01 = 0.f, v10 = 0.f, v11 = 0.f;
    if (n < 27) {
        const float* wb = woff + (size_t)n*CH*KTAPS + tap;
        v00 = wb[(size_t)(c0    )*KTAPS];
        v01 = wb[(size_t)(c0 + 1)*KTAPS];
        v10 = wb[(size_t)(c0 + 8)*KTAPS];
        v11 = wb[(size_t)(c0 + 9)*KTAPS];
    }
    uint16_t h00,l00,h01,l01,h10,l10,h11,l11;
    split_bf16(v00,h00,l00); split_bf16(v01,h01,l01);
    split_bf16(v10,h10,l10); split_bf16(v11,h11,l11);
    size_t o = (size_t)layer*36*512 + idx;
    g_bwoh[o] = make_uint2((uint32_t)h00 | ((uint32_t)h01 << 16),
                           (uint32_t)h10 | ((uint32_t)h11 << 16));
    g_bwol[o] = make_uint2((uint32_t)l00 | ((uint32_t)l01 << 16),
                           (uint32_t)l10 | ((uint32_t)l11 << 16));
}

// ====================== layout transposes ======================
__global__ void nchw_to_nhwc_k(const float* __restrict__ src) {
    __shared__ float t[32][33];
    int b  = blockIdx.z;
    int p0 = blockIdx.x*32, c0 = blockIdx.y*32;
    int tx = threadIdx.x,  ty = threadIdx.y;
    #pragma unroll
    for (int i = 0; i < 32; i += 8)
        t[ty+i][tx] = src[(size_t)(b*CH + c0+ty+i)*HW + p0 + tx];
    __syncthreads();
    #pragma unroll
    for (int i = 0; i < 32; i += 8)
        g_xT[(size_t)(b*HW + p0+ty+i)*CH + c0 + tx] = t[tx][ty+i];
}

__global__ void nhwc_to_nchw_k(float* __restrict__ dst) {
    __shared__ float t[32][33];
    int b  = blockIdx.z;
    int p0 = blockIdx.x*32, c0 = blockIdx.y*32;
    int tx = threadIdx.x,  ty = threadIdx.y;
    #pragma unroll
    for (int i = 0; i < 32; i += 8)
        t[ty+i][tx] = g_h2T[(size_t)(b*HW + p0+ty+i)*CH + c0 + tx];
    __syncthreads();
    #pragma unroll
    for (int i = 0; i < 32; i += 8)
        dst[(size_t)(b*CH + c0+ty+i)*HW + p0 + tx] = t[tx][ty+i];
}

// ====================== sample coordinates + bilinear weights ======================
__global__ void coords_k() {
    int idx = blockIdx.x*256 + threadIdx.x;
    if (idx >= MROWS*KTAPS) return;
    int tap = idx % KTAPS;
    int gp  = idx / KTAPS;
    int p   = gp % HW;
    int y   = p / WW, x = p % WW;
    const float* om = g_om + (size_t)gp*NOFF;
    float dy = om[2*tap], dx = om[2*tap + 1];
    float m  = 1.0f / (1.0f + expf(-om[18 + tap]));
    float ys = (float)(y + tap/3 - 1) + dy;
    float xs = (float)(x + tap%3 - 1) + dx;
    float fy0 = floorf(ys), fx0 = floorf(xs);
    int y0 = (int)fy0, x0 = (int)fx0;
    int y1 = y0 + 1,   x1 = x0 + 1;
    float wy1 = ys - fy0, wx1 = xs - fx0;
    float wy0 = 1.0f - wy1, wx0 = 1.0f - wx1;
    int y0c = min(max(y0,0),HH-1), y1c = min(max(y1,0),HH-1);
    int x0c = min(max(x0,0),WW-1), x1c = min(max(x1,0),WW-1);
    float vy0 = ((unsigned)y0 < HH) ? 1.0f : 0.0f;
    float vy1 = ((unsigned)y1 < HH) ? 1.0f : 0.0f;
    float vx0 = ((unsigned)x0 < WW) ? 1.0f : 0.0f;
    float vx1 = ((unsigned)x1 < WW) ? 1.0f : 0.0f;
    SInfo s;
    s.i0 = y0c*WW + x0c;  s.w0 = wy0*wx0*m*vy0*vx0;
    s.i1 = y0c*WW + x1c;  s.w1 = wy0*wx1*m*vy0*vx1;
    s.i2 = y1c*WW + x0c;  s.w2 = wy1*wx0*m*vy1*vx0;
    s.i3 = y1c*WW + x1c;  s.w3 = wy1*wx1*m*vy1*vx1;
    g_sinfo[idx] = s;
}

// ====================== offset conv: mma.sync bf16x3, N=32 ======================
// CTA: 128 px x 32 N, grid 144. 8 warps, warp tile 16(M) x 32(N). Plain im2col A.
#define OA_H 0
#define OA_L 16384
#define OB_H 32768
#define OB_L 36864
#define OFF_SMEM (40960 + 1024)

__launch_bounds__(256, 1)
__global__ void gemm_off_mma(int layer, const float* __restrict__ bias) {
    extern __shared__ unsigned char dsm[];
    uint32_t raw = smem_u32(dsm);
    uint32_t sb  = (raw + 1023u) & ~1023u;
    unsigned char* smp = dsm + (sb - raw);

    int tid = threadIdx.x, wid = tid >> 5, lane = tid & 31;
    int bm  = blockIdx.x;
    const float* in = layer ? g_h1T : g_xT;
    const uint2* bwh = g_bwoh + (size_t)layer*36*512;
    const uint2* bwl = g_bwol + (size_t)layer*36*512;

    int c4 = tid & 15;                      // 4-ch quad within 64-ch group
    int pg = tid >> 4;                      // 8-px group
    int b  = (bm*128) / HW;
    int pbase = bm*128 - b*HW;
    const float* inb = in + (size_t)b*HW*CH;

    float acc[4][4];
    #pragma unroll
    for (int i = 0; i < 4; i++)
        #pragma unroll
        for (int j = 0; j < 4; j++) acc[i][j] = 0.0f;

    uint32_t a_rel = (uint32_t)((wid*16 + (lane & 15))*128 + (lane >> 4)*16);

    for (int g = 0; g < 4; g++) {
        #pragma unroll 1
        for (int tap = 0; tap < 9; tap++) {
            int blk = tap*4 + g;
            int cc  = g*64 + c4*4;
            int dy  = tap/3 - 1, dx = tap%3 - 1;
            float4 av[8];
            #pragma unroll
            for (int i = 0; i < 8; i++) {
                int px = pg*8 + i;
                int p  = pbase + px;
                int y  = p / WW, x = p - y*WW;
                int ny = y + dy, nx = x + dx;
                bool valid = ((unsigned)ny < HH) & ((unsigned)nx < WW);
                av[i] = valid ? *(const float4*)(inb + (size_t)(ny*WW + nx)*CH + cc)
                              : make_float4(0.f,0.f,0.f,0.f);
            }
            __syncthreads();
            // B via cp.async (4KB per split)
            CP_ASYNC16(sb + OB_H + tid*16, (const void*)((const uint4*)(bwh + (size_t)blk*512) + tid));
            CP_ASYNC16(sb + OB_L + tid*16, (const void*)((const uint4*)(bwl + (size_t)blk*512) + tid));
            CP_COMMIT();
            // A split + store
            #pragma unroll
            for (int i = 0; i < 8; i++) {
                int px = pg*8 + i;
                uint16_t h0,l0,h1,l1,h2,l2,h3,l3;
                split_bf16(av[i].x,h0,l0); split_bf16(av[i].y,h1,l1);
                split_bf16(av[i].z,h2,l2); split_bf16(av[i].w,h3,l3);
                uint32_t so = SW128((uint32_t)(px*128 + c4*8));
                *(uint2*)(smp + OA_H + so) =
                    make_uint2((uint32_t)h0 | ((uint32_t)h1 << 16),
                               (uint32_t)h2 | ((uint32_t)h3 << 16));
                *(uint2*)(smp + OA_L + so) =
                    make_uint2((uint32_t)l0 | ((uint32_t)l1 << 16),
                               (uint32_t)l2 | ((uint32_t)l3 << 16));
            }
            CP_WAIT0();
            __syncthreads();

            #pragma unroll
            for (int kb = 0; kb < 4; kb++) {
                uint2 bh[4], bl[4];
                #pragma unroll
                for (int nb = 0; nb < 4; nb++) {
                    uint32_t boff = (uint32_t)(((kb*4 + nb)*32 + lane)*8);
                    bh[nb] = *(const uint2*)(smp + OB_H + boff);
                    bl[nb] = *(const uint2*)(smp + OB_L + boff);
                }
                uint32_t aoff = SW128(a_rel + (uint32_t)(kb*32));
                uint32_t ah0,ah1,ah2,ah3, al0,al1,al2,al3;
                LDSM4(ah0,ah1,ah2,ah3, sb + OA_H + aoff);
                LDSM4(al0,al1,al2,al3, sb + OA_L + aoff);
                #pragma unroll
                for (int nb = 0; nb < 4; nb++) {
                    MMA16816(acc[nb], ah0,ah1,ah2,ah3, bh[nb].x, bh[nb].y);
                    MMA16816(acc[nb], al0,al1,al2,al3, bh[nb].x, bh[nb].y);
                    MMA16816(acc[nb], ah0,ah1,ah2,ah3, bl[nb].x, bl[nb].y);
                }
            }
        }
    }

    // epilogue: + bias, write g_om
    int crow = lane >> 2, ccol = (lane & 3)*2;
    int row0 = bm*128 + wid*16 + crow;
    #pragma unroll
    for (int nb = 0; nb < 4; nb++) {
        int col = nb*8 + ccol;
        float bv0 = (col     < 27) ? __ldg(bias + col)     : 0.0f;
        float bv1 = (col + 1 < 27) ? __ldg(bias + col + 1) : 0.0f;
        *(float2*)&g_om[(size_t)row0*NOFF + col] =
            make_float2(acc[nb][0] + bv0, acc[nb][1] + bv1);
        *(float2*)&g_om[(size_t)(row0 + 8)*NOFF + col] =
            make_float2(acc[nb][2] + bv0, acc[nb][3] + bv1);
    }
}

// ====================== main deformable conv: mma.sync bf16x3, BN=256 ======================
// CTA: 128 px (M) x 256 out-ch (N), grid 144 (1 wave). 8 warps, warp tile 64x64.
// Single-buffer stages: gather->regs, sync, cp.async B + STS A, wait+sync, MMA.
// SMEM: A hi/lo 2x16KB, B hi/lo 2x32KB, SInfo 128*9*32B = 36864B.
#define SA_H 0
#define SA_L 16384
#define SB_H 32768
#define SB_L 65536
#define SINF 98304
#define MAIN_SMEM (98304 + 36864 + 1024)
#define NSTAGE 36

__launch_bounds__(256, 1)
__global__ void gemm_main_mma(int layer) {
    extern __shared__ unsigned char dsm[];
    uint32_t raw = smem_u32(dsm);
    uint32_t sb  = (raw + 1023u) & ~1023u;
    unsigned char* smp = dsm + (sb - raw);

    int tid  = threadIdx.x;
    int wid  = tid >> 5, lane = tid & 31;
    int wm   = wid & 1;                          // M warp (0..1) -> 64 rows
    int wn   = wid >> 1;                         // N warp (0..3) -> 64 cols
    int bm   = blockIdx.x;                       // 144 M tiles

    const float* in   = layer ? g_h1T : g_xT;
    float*       outF = layer ? g_h2T : g_h1T;
    const uint2* bwh  = g_bwmh + (size_t)layer*36*4096;
    const uint2* bwl  = g_bwml + (size_t)layer*36*4096;

    int c4 = tid & 15;                           // channel quad (16 x 4 = 64 ch)
    int pg = tid >> 4;                           // pixel group (16 x 8 = 128 px)
    int b  = (bm*128) / HW;
    const float* inb = in + (size_t)b*HW*CH;

    // preload SInfo for this tile into smem (reused by all 4 channel groups)
    SInfo* sinfo_s = (SInfo*)(smp + SINF);
    {
        const SInfo* sg = g_sinfo + (size_t)(bm*128)*KTAPS;
        for (int i = tid; i < 128*KTAPS; i += 256) sinfo_s[i] = sg[i];
    }
    __syncthreads();

    float acc[4][8][4];
    #pragma unroll
    for (int i = 0; i < 4; i++)
        #pragma unroll
        for (int j = 0; j < 8; j++)
            #pragma unroll
            for (int k = 0; k < 4; k++) acc[i][j][k] = 0.0f;

    uint32_t a_rel = (uint32_t)((wm*64 + (lane & 15))*128 + (lane >> 4)*16);

    for (int g = 0; g < 4; g++) {
        #pragma unroll 1
        for (int tap = 0; tap < 9; tap++) {
            int blk = tap*4 + g;
            int cc  = g*64 + c4*4;
            // ---- gather + blend into regs ----
            float v[32];
            #pragma unroll
            for (int i = 0; i < 8; i++) {
                int px = pg*8 + i;
                SInfo s = sinfo_s[px*KTAPS + tap];
                float4 a0 = *(const float4*)(inb + (size_t)s.i0*CH + cc);
                float4 a1 = *(const float4*)(inb + (size_t)s.i1*CH + cc);
                float4 a2 = *(const float4*)(inb + (size_t)s.i2*CH + cc);
                float4 a3 = *(const float4*)(inb + (size_t)s.i3*CH + cc);
                v[i*4+0] = s.w0*a0.x + s.w1*a1.x + s.w2*a2.x + s.w3*a3.x;
                v[i*4+1] = s.w0*a0.y + s.w1*a1.y + s.w2*a2.y + s.w3*a3.y;
                v[i*4+2] = s.w0*a0.z + s.w1*a1.z + s.w2*a2.z + s.w3*a3.z;
                v[i*4+3] = s.w0*a0.w + s.w1*a1.w + s.w2*a2.w + s.w3*a3.w;
            }
            __syncthreads();
            // ---- B via cp.async (32KB per split, 16 per thread) ----
            {
                const uint4* sH = (const uint4*)(bwh + (size_t)blk*4096);
                const uint4* sL = (const uint4*)(bwl + (size_t)blk*4096);
                #pragma unroll
                for (int it = 0; it < 8; it++) {
                    uint32_t u = tid + it*256;
                    CP_ASYNC16(sb + SB_H + u*16, (const void*)(sH + u));
                    CP_ASYNC16(sb + SB_L + u*16, (const void*)(sL + u));
                }
                CP_COMMIT();
            }
            // ---- A split + store ----
            #pragma unroll
            for (int i = 0; i < 8; i++) {
                int px = pg*8 + i;
                uint16_t h0,l0,h1,l1,h2,l2,h3,l3;
                split_bf16(v[i*4+0],h0,l0); split_bf16(v[i*4+1],h1,l1);
                split_bf16(v[i*4+2],h2,l2); split_bf16(v[i*4+3],h3,l3);
                uint32_t so = SW128((uint32_t)(px*128 + c4*8));
                *(uint2*)(smp + SA_H + so) =
                    make_uint2((uint32_t)h0 | ((uint32_t)h1 << 16),
                               (uint32_t)h2 | ((uint32_t)h3 << 16));
                *(uint2*)(smp + SA_L + so) =
                    make_uint2((uint32_t)l0 | ((uint32_t)l1 << 16),
                               (uint32_t)l2 | ((uint32_t)l3 << 16));
            }
            CP_WAIT0();
            __syncthreads();

            // ---- compute: 4 k16 steps x 4 m16 x 8 n8 x 3 splits ----
            #pragma unroll
            for (int kb = 0; kb < 4; kb++) {
                uint2 bh[8], bl[8];
                #pragma unroll
                for (int nb = 0; nb < 8; nb++) {
                    uint32_t boff = (uint32_t)(((kb*32 + wn*8 + nb)*32 + lane)*8);
                    bh[nb] = *(const uint2*)(smp + SB_H + boff);
                    bl[nb] = *(const uint2*)(smp + SB_L + boff);
                }
                #pragma unroll
                for (int mi = 0; mi < 4; mi++) {
                    uint32_t aoff = SW128(a_rel + (uint32_t)(mi*2048 + kb*32));
                    uint32_t ah0,ah1,ah2,ah3, al0,al1,al2,al3;
                    LDSM4(ah0,ah1,ah2,ah3, sb + SA_H + aoff);
                    LDSM4(al0,al1,al2,al3, sb + SA_L + aoff);
                    #pragma unroll
                    for (int nb = 0; nb < 8; nb++) {
                        MMA16816(acc[mi][nb], ah0,ah1,ah2,ah3, bh[nb].x, bh[nb].y);
                        MMA16816(acc[mi][nb], al0,al1,al2,al3, bh[nb].x, bh[nb].y);
                        MMA16816(acc[mi][nb], ah0,ah1,ah2,ah3, bl[nb].x, bl[nb].y);
                    }
                }
            }
        }
    }

    // ---- epilogue: ReLU, fp32 NHWC ----
    int crow = lane >> 2, ccol = (lane & 3)*2;
    #pragma unroll
    for (int mi = 0; mi < 4; mi++) {
        int px0 = bm*128 + wm*64 + mi*16;
        #pragma unroll
        for (int nb = 0; nb < 8; nb++) {
            int n = wn*64 + nb*8 + ccol;
            float* o0 = outF + (size_t)(px0 + crow    )*OUTC + n;
            float* o1 = outF + (size_t)(px0 + crow + 8)*OUTC + n;
            *(float2*)o0 = make_float2(fmaxf(acc[mi][nb][0], 0.f), fmaxf(acc[mi][nb][1], 0.f));
            *(float2*)o1 = make_float2(fmaxf(acc[mi][nb][2], 0.f), fmaxf(acc[mi][nb][3], 0.f));
        }
    }
}

// ====================== launch ======================
extern "C" void kernel_launch(void* const* d_in, const int* in_sizes, int n_in,
                              void* d_out, int out_size) {
    (void)in_sizes; (void)n_in; (void)out_size;
    const float* x      = (const float*)d_in[0];
    const float* w_off0 = (const float*)d_in[1];
    const float* b_off0 = (const float*)d_in[2];
    const float* w0     = (const float*)d_in[3];
    const float* w_off1 = (const float*)d_in[4];
    const float* b_off1 = (const float*)d_in[5];
    const float* w1     = (const float*)d_in[6];
    float* out = (float*)d_out;

    cudaFuncSetAttribute(gemm_main_mma, cudaFuncAttributeMaxDynamicSharedMemorySize, MAIN_SMEM);
    cudaFuncSetAttribute(gemm_off_mma,  cudaFuncAttributeMaxDynamicSharedMemorySize, OFF_SMEM);

    prep_off_mma <<<(36*512 + 255)/256, 256>>>(w_off0, 0);
    prep_off_mma <<<(36*512 + 255)/256, 256>>>(w_off1, 1);
    prep_main_mma<<<(36*4096 + 255)/256, 256>>>(w0, 0);
    prep_main_mma<<<(36*4096 + 255)/256, 256>>>(w1, 1);

    dim3 tb(32, 8);
    dim3 tg(HW/32, CH/32, BATCH);
    nchw_to_nhwc_k<<<tg, tb>>>(x);

    // layer 1
    gemm_off_mma <<<MROWS/128, 256, OFF_SMEM >>>(0, b_off0);
    coords_k     <<<(MROWS*KTAPS + 255)/256, 256>>>();
    gemm_main_mma<<<MROWS/128, 256, MAIN_SMEM>>>(0);

    // layer 2
    gemm_off_mma <<<MROWS/128, 256, OFF_SMEM >>>(1, b_off1);
    coords_k     <<<(MROWS*KTAPS + 255)/256, 256>>>();
    gemm_main_mma<<<MROWS/128, 256, MAIN_SMEM>>>(1);

    nhwc_to_nchw_k<<<tg, tb>>>(out);
}

// round 12
// speedup vs baseline: 1.6478x; 1.0348x over previous
#include <cuda_runtime.h>
#include <cuda_bf16.h>
#include <stdint.h>
#include <math.h>

#define BATCH 2
#define CH    256
#define HH    96
#define WW    96
#define HW    (HH*WW)        // 9216
#define OUTC  256
#define KTAPS 9
#define KDIM  (KTAPS*CH)     // 2304
#define MROWS (BATCH*HW)     // 18432
#define NOFF  32             // 27 padded to 32

#define SW128(o) ((o) ^ ((((o) >> 3) & 0x70)))

struct __align__(16) SInfo { int i0,i1,i2,i3; float w0,w1,w2,w3; };

// ---- scratch (device globals: allocation-free) ----
__device__ float g_xT [MROWS*CH];        // x NHWC fp32
__device__ float g_h1T[MROWS*CH];        // layer-1 out NHWC fp32
__device__ float g_h2T[MROWS*CH];        // layer-2 out NHWC fp32
__device__ float g_om [MROWS*NOFF];      // offset-conv out (27 used)
__device__ SInfo g_sinfo[MROWS*KTAPS];   // bilinear indices+weights
// main weights in mma-B-fragment order, bf16 hi/lo:
//   [layer][blk36 = tap*4+g][kb4][nb32][lane32] uint2{pack(k0,k1), pack(k0+8,k1+8)}
__device__ uint2 g_bwmh[2*36*4096];
__device__ uint2 g_bwml[2*36*4096];
// offset weights, same frag order, N=32: [layer][blk36][kb4][nb4][lane32]
__device__ uint2 g_bwoh[2*36*512];
__device__ uint2 g_bwol[2*36*512];

// ====================== helpers ======================
__device__ __forceinline__ uint32_t smem_u32(const void* p) {
    uint32_t a;
    asm("{ .reg .u64 t; cvta.to.shared.u64 t, %1; cvt.u32.u64 %0, t; }" : "=r"(a) : "l"(p));
    return a;
}

__device__ __forceinline__ void split_bf16(float v, uint16_t& h, uint16_t& l) {
    __nv_bfloat16 hb = __float2bfloat16_rn(v);
    float lo = v - __bfloat162float(hb);
    __nv_bfloat16 lb = __float2bfloat16_rn(lo);
    h = __bfloat16_as_ushort(hb);
    l = __bfloat16_as_ushort(lb);
}

#define LDSM4(r0,r1,r2,r3, addr)                                                    \
    asm volatile("ldmatrix.sync.aligned.m8n8.x4.shared.b16 {%0,%1,%2,%3}, [%4];"    \
        : "=r"(r0), "=r"(r1), "=r"(r2), "=r"(r3) : "r"(addr))

#define MMA16816(d, a0,a1,a2,a3, b0,b1)                                             \
    asm volatile("mma.sync.aligned.m16n8k16.row.col.f32.bf16.bf16.f32 "             \
        "{%0,%1,%2,%3}, {%4,%5,%6,%7}, {%8,%9}, {%0,%1,%2,%3};"                     \
        : "+f"((d)[0]), "+f"((d)[1]), "+f"((d)[2]), "+f"((d)[3])                    \
        : "r"(a0), "r"(a1), "r"(a2), "r"(a3), "r"(b0), "r"(b1))

#define CP_ASYNC16(dst, src) \
    asm volatile("cp.async.cg.shared.global [%0], [%1], 16;" :: "r"(dst), "l"(src))
#define CP_COMMIT() asm volatile("cp.async.commit_group;" ::: "memory")
#define CP_WAIT0()  asm volatile("cp.async.wait_group 0;" ::: "memory")

// ====================== weight prep ======================
__global__ void prep_main_mma(const float* __restrict__ w, int layer) {
    int idx = blockIdx.x*256 + threadIdx.x;           // 36*4096 = 147456
    if (idx >= 36*4096) return;
    int lane = idx & 31;
    int nb   = (idx >> 5) & 31;
    int kb   = (idx >> 10) & 3;
    int blk  = idx >> 12;
    int tap  = blk >> 2, g = blk & 3;
    int n    = nb*8 + (lane >> 2);
    int c0   = g*64 + kb*16 + (lane & 3)*2;
    const float* wb = w + (size_t)n*CH*KTAPS + tap;
    float v00 = wb[(size_t)(c0    )*KTAPS];
    float v01 = wb[(size_t)(c0 + 1)*KTAPS];
    float v10 = wb[(size_t)(c0 + 8)*KTAPS];
    float v11 = wb[(size_t)(c0 + 9)*KTAPS];
    uint16_t h00,l00,h01,l01,h10,l10,h11,l11;
    split_bf16(v00,h00,l00); split_bf16(v01,h01,l01);
    split_bf16(v10,h10,l10); split_bf16(v11,h11,l11);
    size_t o = (size_t)layer*36*4096 + idx;
    g_bwmh[o] = make_uint2((uint32_t)h00 | ((uint32_t)h01 << 16),
                           (uint32_t)h10 | ((uint32_t)h11 << 16));
    g_bwml[o] = make_uint2((uint32_t)l00 | ((uint32_t)l01 << 16),
                           (uint32_t)l10 | ((uint32_t)l11 << 16));
}

__global__ void prep_off_mma(const float* __restrict__ woff, int layer) {
    int idx = blockIdx.x*256 + threadIdx.x;           // 36*512 = 18432
    if (idx >= 36*512) return;
    int lane = idx & 31;
    int nb   = (idx >> 5) & 3;
    int kb   = (idx >> 7) & 3;
    int blk  = idx >> 9;
    int tap  = blk >> 2, g = blk & 3;
    int n    = nb*8 + (lane >> 2);
    int c0   = g*64 + kb*16 + (lane & 3)*2;
    float v00 = 0.f, v01 = 0.f, v10 = 0.f, v11 = 0.f;
    if (n < 27) {
        const float* wb = woff + (size_t)n*CH*KTAPS + tap;
        v00 = wb[(size_t)(c0    )*KTAPS];
        v01 = wb[(size_t)(c0 + 1)*KTAPS];
        v10 = wb[(size_t)(c0 + 8)*KTAPS];
        v11 = wb[(size_t)(c0 + 9)*KTAPS];
    }
    uint16_t h00,l00,h01,l01,h10,l10,h11,l11;
    split_bf16(v00,h00,l00); split_bf16(v01,h01,l01);
    split_bf16(v10,h10,l10); split_bf16(v11,h11,l11);
    size_t o = (size_t)layer*36*512 + idx;
    g_bwoh[o] = make_uint2((uint32_t)h00 | ((uint32_t)h01 << 16),
                           (uint32_t)h10 | ((uint32_t)h11 << 16));
    g_bwol[o] = make_uint2((uint32_t)l00 | ((uint32_t)l01 << 16),
                           (uint32_t)l10 | ((uint32_t)l11 << 16));
}

// ====================== layout transposes ======================
__global__ void nchw_to_nhwc_k(const float* __restrict__ src) {
    __shared__ float t[32][33];
    int b  = blockIdx.z;
    int p0 = blockIdx.x*32, c0 = blockIdx.y*32;
    int tx = threadIdx.x,  ty = threadIdx.y;
    #pragma unroll
    for (int i = 0; i < 32; i += 8)
        t[ty+i][tx] = src[(size_t)(b*CH + c0+ty+i)*HW + p0 + tx];
    __syncthreads();
    #pragma unroll
    for (int i = 0; i < 32; i += 8)
        g_xT[(size_t)(b*HW + p0+ty+i)*CH + c0 + tx] = t[tx][ty+i];
}

__global__ void nhwc_to_nchw_k(float* __restrict__ dst) {
    __shared__ float t[32][33];
    int b  = blockIdx.z;
    int p0 = blockIdx.x*32, c0 = blockIdx.y*32;
    int tx = threadIdx.x,  ty = threadIdx.y;
    #pragma unroll
    for (int i = 0; i < 32; i += 8)
        t[ty+i][tx] = g_h2T[(size_t)(b*HW + p0+ty+i)*CH + c0 + tx];
    __syncthreads();
    #pragma unroll
    for (int i = 0; i < 32; i += 8)
        dst[(size_t)(b*CH + c0+ty+i)*HW + p0 + tx] = t[tx][ty+i];
}

// ====================== sample coordinates + bilinear weights ======================
__global__ void coords_k() {
    int idx = blockIdx.x*256 + threadIdx.x;
    if (idx >= MROWS*KTAPS) return;
    int tap = idx % KTAPS;
    int gp  = idx / KTAPS;
    int p   = gp % HW;
    int y   = p / WW, x = p % WW;
    const float* om = g_om + (size_t)gp*NOFF;
    float dy = om[2*tap], dx = om[2*tap + 1];
    float m  = 1.0f / (1.0f + expf(-om[18 + tap]));
    float ys = (float)(y + tap/3 - 1) + dy;
    float xs = (float)(x + tap%3 - 1) + dx;
    float fy0 = floorf(ys), fx0 = floorf(xs);
    int y0 = (int)fy0, x0 = (int)fx0;
    int y1 = y0 + 1,   x1 = x0 + 1;
    float wy1 = ys - fy0, wx1 = xs - fx0;
    float wy0 = 1.0f - wy1, wx0 = 1.0f - wx1;
    int y0c = min(max(y0,0),HH-1), y1c = min(max(y1,0),HH-1);
    int x0c = min(max(x0,0),WW-1), x1c = min(max(x1,0),WW-1);
    float vy0 = ((unsigned)y0 < HH) ? 1.0f : 0.0f;
    float vy1 = ((unsigned)y1 < HH) ? 1.0f : 0.0f;
    float vx0 = ((unsigned)x0 < WW) ? 1.0f : 0.0f;
    float vx1 = ((unsigned)x1 < WW) ? 1.0f : 0.0f;
    SInfo s;
    s.i0 = y0c*WW + x0c;  s.w0 = wy0*wx0*m*vy0*vx0;
    s.i1 = y0c*WW + x1c;  s.w1 = wy0*wx1*m*vy0*vx1;
    s.i2 = y1c*WW + x0c;  s.w2 = wy1*wx0*m*vy1*vx0;
    s.i3 = y1c*WW + x1c;  s.w3 = wy1*wx1*m*vy1*vx1;
    g_sinfo[idx] = s;
}

// ====================== offset conv: mma.sync bf16x3, N=32, BM=64 ======================
// CTA: 64 px x 32 N, grid 288 (2+ CTAs/SM). 8 warps: wm=wid&3 (m16), wn=wid>>2 (2 n8).
#define OA_H 0
#define OA_L 8192
#define OB_H 16384
#define OB_L 20480
#define OFF_SMEM (24576 + 1024)

__launch_bounds__(256, 2)
__global__ void gemm_off_mma(int layer, const float* __restrict__ bias) {
    extern __shared__ unsigned char dsm[];
    uint32_t raw = smem_u32(dsm);
    uint32_t sb  = (raw + 1023u) & ~1023u;
    unsigned char* smp = dsm + (sb - raw);

    int tid = threadIdx.x, wid = tid >> 5, lane = tid & 31;
    int wm  = wid & 3, wn = wid >> 2;
    int bm  = blockIdx.x;                   // 288 tiles of 64 px
    const float* in = layer ? g_h1T : g_xT;
    const uint2* bwh = g_bwoh + (size_t)layer*36*512;
    const uint2* bwl = g_bwol + (size_t)layer*36*512;

    int c4 = tid & 15;                      // 4-ch quad within 64-ch group
    int pg = tid >> 4;                      // 4-px group
    int b  = (bm*64) / HW;
    int pbase = bm*64 - b*HW;
    const float* inb = in + (size_t)b*HW*CH;

    float acc[2][4];
    #pragma unroll
    for (int i = 0; i < 2; i++)
        #pragma unroll
        for (int j = 0; j < 4; j++) acc[i][j] = 0.0f;

    uint32_t a_rel = (uint32_t)((wm*16 + (lane & 15))*128 + (lane >> 4)*16);

    for (int g = 0; g < 4; g++) {
        #pragma unroll 1
        for (int tap = 0; tap < 9; tap++) {
            int blk = tap*4 + g;
            int cc  = g*64 + c4*4;
            int dy  = tap/3 - 1, dx = tap%3 - 1;
            float4 av[4];
            #pragma unroll
            for (int i = 0; i < 4; i++) {
                int px = pg*4 + i;
                int p  = pbase + px;
                int y  = p / WW, x = p - y*WW;
                int ny = y + dy, nx = x + dx;
                bool valid = ((unsigned)ny < HH) & ((unsigned)nx < WW);
                av[i] = valid ? *(const float4*)(inb + (size_t)(ny*WW + nx)*CH + cc)
                              : make_float4(0.f,0.f,0.f,0.f);
            }
            __syncthreads();
            // B via cp.async (4KB per split; 256 threads x 16B covers hi, repeat for lo)
            CP_ASYNC16(sb + OB_H + tid*16, (const void*)((const uint4*)(bwh + (size_t)blk*512) + tid));
            CP_ASYNC16(sb + OB_L + tid*16, (const void*)((const uint4*)(bwl + (size_t)blk*512) + tid));
            CP_COMMIT();
            // A split + store
            #pragma unroll
            for (int i = 0; i < 4; i++) {
                int px = pg*4 + i;
                uint16_t h0,l0,h1,l1,h2,l2,h3,l3;
                split_bf16(av[i].x,h0,l0); split_bf16(av[i].y,h1,l1);
                split_bf16(av[i].z,h2,l2); split_bf16(av[i].w,h3,l3);
                uint32_t so = SW128((uint32_t)(px*128 + c4*8));
                *(uint2*)(smp + OA_H + so) =
                    make_uint2((uint32_t)h0 | ((uint32_t)h1 << 16),
                               (uint32_t)h2 | ((uint32_t)h3 << 16));
                *(uint2*)(smp + OA_L + so) =
                    make_uint2((uint32_t)l0 | ((uint32_t)l1 << 16),
                               (uint32_t)l2 | ((uint32_t)l3 << 16));
            }
            CP_WAIT0();
            __syncthreads();

            #pragma unroll
            for (int kb = 0; kb < 4; kb++) {
                uint32_t aoff = SW128(a_rel + (uint32_t)(kb*32));
                uint32_t ah0,ah1,ah2,ah3, al0,al1,al2,al3;
                LDSM4(ah0,ah1,ah2,ah3, sb + OA_H + aoff);
                LDSM4(al0,al1,al2,al3, sb + OA_L + aoff);
                #pragma unroll
                for (int j = 0; j < 2; j++) {
                    int nb = wn*2 + j;
                    uint32_t boff = (uint32_t)(((kb*4 + nb)*32 + lane)*8);
                    uint2 bh = *(const uint2*)(smp + OB_H + boff);
                    uint2 bl = *(const uint2*)(smp + OB_L + boff);
                    MMA16816(acc[j], ah0,ah1,ah2,ah3, bh.x, bh.y);
                    MMA16816(acc[j], al0,al1,al2,al3, bh.x, bh.y);
                    MMA16816(acc[j], ah0,ah1,ah2,ah3, bl.x, bl.y);
                }
            }
        }
    }

    // epilogue: + bias, write g_om
    int crow = lane >> 2, ccol = (lane & 3)*2;
    int row0 = bm*64 + wm*16 + crow;
    #pragma unroll
    for (int j = 0; j < 2; j++) {
        int col = (wn*2 + j)*8 + ccol;
        float bv0 = (col     < 27) ? __ldg(bias + col)     : 0.0f;
        float bv1 = (col + 1 < 27) ? __ldg(bias + col + 1) : 0.0f;
        *(float2*)&g_om[(size_t)row0*NOFF + col] =
            make_float2(acc[j][0] + bv0, acc[j][1] + bv1);
        *(float2*)&g_om[(size_t)(row0 + 8)*NOFF + col] =
            make_float2(acc[j][2] + bv0, acc[j][3] + bv1);
    }
}

// ====================== main deformable conv: mma.sync bf16x3, BM=64 BN=256 ======================
// CTA: 64 px (M) x 256 out-ch (N), grid 288 (2 CTAs/SM -> cross-CTA phase overlap).
// SMEM: A hi/lo 2x8KB, B hi/lo 2x32KB, SInfo 64*9*32B = 18432B -> ~100KB.
#define SA_H 0
#define SA_L 8192
#define SB_H 16384
#define SB_L 49152
#define SINF 81920
#define MAIN_SMEM (81920 + 18432 + 1024)

__launch_bounds__(256, 2)
__global__ void gemm_main_mma(int layer) {
    extern __shared__ unsigned char dsm[];
    uint32_t raw = smem_u32(dsm);
    uint32_t sb  = (raw + 1023u) & ~1023u;
    unsigned char* smp = dsm + (sb - raw);

    int tid  = threadIdx.x;
    int wid  = tid >> 5, lane = tid & 31;
    int wm   = wid & 1;                          // M warp (0..1) -> 32 rows
    int wn   = wid >> 1;                         // N warp (0..3) -> 64 cols
    int bm   = blockIdx.x;                       // 288 M tiles of 64 px

    const float* in   = layer ? g_h1T : g_xT;
    float*       outF = layer ? g_h2T : g_h1T;
    const uint2* bwh  = g_bwmh + (size_t)layer*36*4096;
    const uint2* bwl  = g_bwml + (size_t)layer*36*4096;

    int c4 = tid & 15;                           // channel quad (16 x 4 = 64 ch)
    int pg = tid >> 4;                           // pixel group (16 x 4 = 64 px)
    int b  = (bm*64) / HW;
    const float* inb = in + (size_t)b*HW*CH;

    // preload SInfo for this tile into smem (reused by all 4 channel groups)
    SInfo* sinfo_s = (SInfo*)(smp + SINF);
    {
        const SInfo* sg = g_sinfo + (size_t)(bm*64)*KTAPS;
        for (int i = tid; i < 64*KTAPS; i += 256) sinfo_s[i] = sg[i];
    }
    __syncthreads();

    float acc[2][8][4];
    #pragma unroll
    for (int i = 0; i < 2; i++)
        #pragma unroll
        for (int j = 0; j < 8; j++)
            #pragma unroll
            for (int k = 0; k < 4; k++) acc[i][j][k] = 0.0f;

    uint32_t a_rel = (uint32_t)((wm*32 + (lane & 15))*128 + (lane >> 4)*16);

    for (int g = 0; g < 4; g++) {
        #pragma unroll 1
        for (int tap = 0; tap < 9; tap++) {
            int blk = tap*4 + g;
            int cc  = g*64 + c4*4;
            // ---- gather + blend into regs (4 px x 4 ch) ----
            float v[16];
            #pragma unroll
            for (int i = 0; i < 4; i++) {
                int px = pg*4 + i;
                SInfo s = sinfo_s[px*KTAPS + tap];
                float4 a0 = *(const float4*)(inb + (size_t)s.i0*CH + cc);
                float4 a1 = *(const float4*)(inb + (size_t)s.i1*CH + cc);
                float4 a2 = *(const float4*)(inb + (size_t)s.i2*CH + cc);
                float4 a3 = *(const float4*)(inb + (size_t)s.i3*CH + cc);
                v[i*4+0] = s.w0*a0.x + s.w1*a1.x + s.w2*a2.x + s.w3*a3.x;
                v[i*4+1] = s.w0*a0.y + s.w1*a1.y + s.w2*a2.y + s.w3*a3.y;
                v[i*4+2] = s.w0*a0.z + s.w1*a1.z + s.w2*a2.z + s.w3*a3.z;
                v[i*4+3] = s.w0*a0.w + s.w1*a1.w + s.w2*a2.w + s.w3*a3.w;
            }
            __syncthreads();
            // ---- B via cp.async (32KB per split, 8 uint4 per thread per split) ----
            {
                const uint4* sH = (const uint4*)(bwh + (size_t)blk*4096);
                const uint4* sL = (const uint4*)(bwl + (size_t)blk*4096);
                #pragma unroll
                for (int it = 0; it < 8; it++) {
                    uint32_t u = tid + it*256;
                    CP_ASYNC16(sb + SB_H + u*16, (const void*)(sH + u));
                    CP_ASYNC16(sb + SB_L + u*16, (const void*)(sL + u));
                }
                CP_COMMIT();
            }
            // ---- A split + store ----
            #pragma unroll
            for (int i = 0; i < 4; i++) {
                int px = pg*4 + i;
                uint16_t h0,l0,h1,l1,h2,l2,h3,l3;
                split_bf16(v[i*4+0],h0,l0); split_bf16(v[i*4+1],h1,l1);
                split_bf16(v[i*4+2],h2,l2); split_bf16(v[i*4+3],h3,l3);
                uint32_t so = SW128((uint32_t)(px*128 + c4*8));
                *(uint2*)(smp + SA_H + so) =
                    make_uint2((uint32_t)h0 | ((uint32_t)h1 << 16),
                               (uint32_t)h2 | ((uint32_t)h3 << 16));
                *(uint2*)(smp + SA_L + so) =
                    make_uint2((uint32_t)l0 | ((uint32_t)l1 << 16),
                               (uint32_t)l2 | ((uint32_t)l3 << 16));
            }
            CP_WAIT0();
            __syncthreads();

            // ---- compute: 4 k16 steps x 2 m16 x 8 n8 x 3 splits ----
            #pragma unroll
            for (int kb = 0; kb < 4; kb++) {
                uint2 bh[8], bl[8];
                #pragma unroll
                for (int nb = 0; nb < 8; nb++) {
                    uint32_t boff = (uint32_t)(((kb*32 + wn*8 + nb)*32 + lane)*8);
                    bh[nb] = *(const uint2*)(smp + SB_H + boff);
                    bl[nb] = *(const uint2*)(smp + SB_L + boff);
                }
                #pragma unroll
                for (int mi = 0; mi < 2; mi++) {
                    uint32_t aoff = SW128(a_rel + (uint32_t)(mi*2048 + kb*32));
                    uint32_t ah0,ah1,ah2,ah3, al0,al1,al2,al3;
                    LDSM4(ah0,ah1,ah2,ah3, sb + SA_H + aoff);
                    LDSM4(al0,al1,al2,al3, sb + SA_L + aoff);
                    #pragma unroll
                    for (int nb = 0; nb < 8; nb++) {
                        MMA16816(acc[mi][nb], ah0,ah1,ah2,ah3, bh[nb].x, bh[nb].y);
                        MMA16816(acc[mi][nb], al0,al1,al2,al3, bh[nb].x, bh[nb].y);
                        MMA16816(acc[mi][nb], ah0,ah1,ah2,ah3, bl[nb].x, bl[nb].y);
                    }
                }
            }
        }
    }

    // ---- epilogue: ReLU, fp32 NHWC ----
    int crow = lane >> 2, ccol = (lane & 3)*2;
    #pragma unroll
    for (int mi = 0; mi < 2; mi++) {
        int px0 = bm*64 + wm*32 + mi*16;
        #pragma unroll
        for (int nb = 0; nb < 8; nb++) {
            int n = wn*64 + nb*8 + ccol;
            float* o0 = outF + (size_t)(px0 + crow    )*OUTC + n;
            float* o1 = outF + (size_t)(px0 + crow + 8)*OUTC + n;
            *(float2*)o0 = make_float2(fmaxf(acc[mi][nb][0], 0.f), fmaxf(acc[mi][nb][1], 0.f));
            *(float2*)o1 = make_float2(fmaxf(acc[mi][nb][2], 0.f), fmaxf(acc[mi][nb][3], 0.f));
        }
    }
}

// ====================== launch ======================
extern "C" void kernel_launch(void* const* d_in, const int* in_sizes, int n_in,
                              void* d_out, int out_size) {
    (void)in_sizes; (void)n_in; (void)out_size;
    const float* x      = (const float*)d_in[0];
    const float* w_off0 = (const float*)d_in[1];
    const float* b_off0 = (const float*)d_in[2];
    const float* w0     = (const float*)d_in[3];
    const float* w_off1 = (const float*)d_in[4];
    const float* b_off1 = (const float*)d_in[5];
    const float* w1     = (const float*)d_in[6];
    float* out = (float*)d_out;

    cudaFuncSetAttribute(gemm_main_mma, cudaFuncAttributeMaxDynamicSharedMemorySize, MAIN_SMEM);
    cudaFuncSetAttribute(gemm_off_mma,  cudaFuncAttributeMaxDynamicSharedMemorySize, OFF_SMEM);

    prep_off_mma <<<(36*512 + 255)/256, 256>>>(w_off0, 0);
    prep_off_mma <<<(36*512 + 255)/256, 256>>>(w_off1, 1);
    prep_main_mma<<<(36*4096 + 255)/256, 256>>>(w0, 0);
    prep_main_mma<<<(36*4096 + 255)/256, 256>>>(w1, 1);

    dim3 tb(32, 8);
    dim3 tg(HW/32, CH/32, BATCH);
    nchw_to_nhwc_k<<<tg, tb>>>(x);

    // layer 1
    gemm_off_mma <<<MROWS/64, 256, OFF_SMEM >>>(0, b_off0);
    coords_k     <<<(MROWS*KTAPS + 255)/256, 256>>>();
    gemm_main_mma<<<MROWS/64, 256, MAIN_SMEM>>>(0);

    // layer 2
    gemm_off_mma <<<MROWS/64, 256, OFF_SMEM >>>(1, b_off1);
    coords_k     <<<(MROWS*KTAPS + 255)/256, 256>>>();
    gemm_main_mma<<<MROWS/64, 256, MAIN_SMEM>>>(1);

    nhwc_to_nchw_k<<<tg, tb>>>(out);
}